// round 1
// baseline (speedup 1.0000x reference)
#include <cuda_runtime.h>
#include <cuda_bf16.h>
#include <cstdint>

// ---------------------------------------------------------------------------
// EdgeDense: z = x @ W + b  (N x 32), then out[e] = w_e * (z[rows[e]] + z[cols[e]])
// N_NODES = 100000, IN = 128, OUT = 32, E = 1.6M
// ---------------------------------------------------------------------------

#define MAX_NODES 100000
#define IN_F 128
#define OUT_F 32

// Scratch: z matrix (12.8 MB) — device global, no allocation allowed.
__device__ float g_z[(size_t)MAX_NODES * OUT_F];
// Index-dtype flag: 1 => indices are int64, 0 => indices are int32.
__device__ int g_idx64;

// ---------------------------------------------------------------------------
// Detect whether edge index buffers are int64 or int32 (JAX x64-off hazard).
// If the data is really int32, reading it as int64 gives v = lo + (hi<<32)
// which is out of [0, n_nodes) whenever hi != 0 — over 4096 words this is
// unambiguous (P[all hi == 0] ~ 0 for uniform indices).
// ---------------------------------------------------------------------------
__global__ void detect_idx_dtype_kernel(const long long* __restrict__ idx,
                                        int n_words, int n_nodes) {
    __shared__ int bad;
    if (threadIdx.x == 0) bad = 0;
    __syncthreads();
    int local_bad = 0;
    for (int i = threadIdx.x; i < n_words; i += blockDim.x) {
        long long v = idx[i];
        if (v < 0 || v >= (long long)n_nodes) local_bad = 1;
    }
    if (local_bad) bad = 1;
    __syncthreads();
    if (threadIdx.x == 0) g_idx64 = bad ? 0 : 1;
}

// ---------------------------------------------------------------------------
// GEMM kernel: one node per thread, 32 fp32 accumulators.
// W (128x32 = 16 KB) lives in smem, read via broadcast LDS.128.
// z tile is staged through padded smem (stride 33) so the global store is
// fully coalesced (direct per-thread row stores would be 32 wavefronts/STG).
// ---------------------------------------------------------------------------
#define GEMM_BLOCK 256

__global__ __launch_bounds__(GEMM_BLOCK)
void gemm_kernel(const float4* __restrict__ x4,   // x as float4: node*32 + kk
                 const float*  __restrict__ W,    // [128][32] row-major
                 const float*  __restrict__ b,    // [32]
                 float* __restrict__ z,
                 int n_nodes) {
    // Shared buffer reused across phases:
    //   phase 1: first 4096 floats = W
    //   phase 2: GEMM_BLOCK * 33 floats = padded z staging
    __shared__ float sbuf[GEMM_BLOCK * 33];

    int tid = threadIdx.x;

    // Load W into smem (coalesced).
    #pragma unroll
    for (int i = tid; i < IN_F * OUT_F; i += GEMM_BLOCK) sbuf[i] = W[i];
    __syncthreads();

    int node = blockIdx.x * GEMM_BLOCK + tid;

    float acc[OUT_F];
    #pragma unroll
    for (int o = 0; o < OUT_F; o++) acc[o] = __ldg(&b[o]);

    if (node < n_nodes) {
        const float4* xr = x4 + (size_t)node * (IN_F / 4);
        #pragma unroll 4
        for (int kk = 0; kk < IN_F / 4; kk++) {
            float4 xv = __ldg(&xr[kk]);
            float xs[4] = {xv.x, xv.y, xv.z, xv.w};
            #pragma unroll
            for (int j = 0; j < 4; j++) {
                const float4* wr =
                    reinterpret_cast<const float4*>(sbuf + (kk * 4 + j) * OUT_F);
                float s = xs[j];
                #pragma unroll
                for (int o4 = 0; o4 < OUT_F / 4; o4++) {
                    float4 wv = wr[o4];   // broadcast LDS.128
                    acc[4 * o4 + 0] = fmaf(s, wv.x, acc[4 * o4 + 0]);
                    acc[4 * o4 + 1] = fmaf(s, wv.y, acc[4 * o4 + 1]);
                    acc[4 * o4 + 2] = fmaf(s, wv.z, acc[4 * o4 + 2]);
                    acc[4 * o4 + 3] = fmaf(s, wv.w, acc[4 * o4 + 3]);
                }
            }
        }
    }

    __syncthreads();   // done reading W region; safe to overwrite sbuf

    // Stage: stride 33 => bank = (tid + o) % 32, conflict-free both ways.
    #pragma unroll
    for (int o = 0; o < OUT_F; o++) sbuf[tid * 33 + o] = acc[o];
    __syncthreads();

    // Coalesced cooperative store of the block's z tile.
    size_t z_base = (size_t)blockIdx.x * GEMM_BLOCK * OUT_F;
    size_t z_limit = (size_t)n_nodes * OUT_F;
    #pragma unroll
    for (int i = tid; i < GEMM_BLOCK * OUT_F; i += GEMM_BLOCK) {
        size_t gi = z_base + i;
        if (gi < z_limit) {
            int ln = i >> 5;      // local node
            int o  = i & 31;
            z[gi] = sbuf[ln * 33 + o];
        }
    }
}

// ---------------------------------------------------------------------------
// Edge kernel: 8 threads per edge, one float4 each. The 8-thread group covers
// the full 128B z row for r and c (one L2 line each); output stores are fully
// coalesced (consecutive threads -> consecutive float4).
// ---------------------------------------------------------------------------
__global__ __launch_bounds__(256)
void edge_kernel(const float* __restrict__ z,
                 const void* __restrict__ rows_raw,
                 const void* __restrict__ cols_raw,
                 const float* __restrict__ vals,
                 float4* __restrict__ out,
                 int n_edges) {
    int gid = blockIdx.x * blockDim.x + threadIdx.x;
    int e = gid >> 3;
    int c = gid & 7;
    if (e >= n_edges) return;

    long long r, cc;
    if (g_idx64) {
        r  = ((const long long*)rows_raw)[e];
        cc = ((const long long*)cols_raw)[e];
    } else {
        r  = ((const int*)rows_raw)[e];
        cc = ((const int*)cols_raw)[e];
    }
    float w = __ldg(&vals[e]);

    const float4* zr = reinterpret_cast<const float4*>(z + r  * OUT_F) + c;
    const float4* zc = reinterpret_cast<const float4*>(z + cc * OUT_F) + c;
    float4 a = __ldg(zr);
    float4 d = __ldg(zc);

    float4 o;
    o.x = w * (a.x + d.x);
    o.y = w * (a.y + d.y);
    o.z = w * (a.z + d.z);
    o.w = w * (a.w + d.w);

    out[(size_t)e * 8 + c] = o;
}

// ---------------------------------------------------------------------------
// Launch. Inputs (metadata order): x, W, b, edge_rows, edge_cols, edge_vals.
// ---------------------------------------------------------------------------
extern "C" void kernel_launch(void* const* d_in, const int* in_sizes, int n_in,
                              void* d_out, int out_size) {
    const float4* x4   = (const float4*)d_in[0];
    const float*  W    = (const float*)d_in[1];
    const float*  b    = (const float*)d_in[2];
    const void*   rows = d_in[3];
    const void*   cols = d_in[4];
    const float*  vals = (const float*)d_in[5];
    float4* out = (float4*)d_out;

    int n_nodes = in_sizes[0] / IN_F;
    int n_edges = in_sizes[3];

    float* z = nullptr;
    cudaGetSymbolAddress((void**)&z, g_z);

    // 1) classify index dtype (int64 vs silently-downcast int32)
    int n_words = n_edges / 2;           // safe for both layouts
    if (n_words > 4096) n_words = 4096;
    detect_idx_dtype_kernel<<<1, 256>>>((const long long*)rows, n_words, n_nodes);

    // 2) z = x @ W + b
    int gemm_blocks = (n_nodes + GEMM_BLOCK - 1) / GEMM_BLOCK;
    gemm_kernel<<<gemm_blocks, GEMM_BLOCK>>>(x4, W, b, z, n_nodes);

    // 3) out[e] = w_e * (z[r] + z[c])
    long long total = (long long)n_edges * 8;
    int edge_blocks = (int)((total + 255) / 256);
    edge_kernel<<<edge_blocks, 256>>>(z, rows, cols, vals, out, n_edges);
}

// round 2
// speedup vs baseline: 1.0853x; 1.0853x over previous
#include <cuda_runtime.h>
#include <cuda_fp16.h>
#include <cstdint>

// ---------------------------------------------------------------------------
// EdgeDense: z = x @ W + b  (N x 32, stored fp16), then
//            out[e] = w_e * (z[rows[e]] + z[cols[e]])   (fp32 out)
// N_NODES = 100000, IN = 128, OUT = 32, E = 1.6M
// ---------------------------------------------------------------------------

#define MAX_NODES 100000
#define IN_F 128
#define OUT_F 32
#define GEMM_BLOCK 256

// z in fp16: 100000 * 32 * 2B = 6.4 MB (fully L2-resident). Device global —
// no allocation allowed.
__device__ __half2 g_zh[(size_t)MAX_NODES * (OUT_F / 2)];
// Index-dtype flag: 1 => indices are int64, 0 => indices are int32.
__device__ int g_idx64;

// Packed fp32x2 FMA (ptxas never auto-fuses; explicit PTX doubles FFMA tput).
#define FMA_F32X2(d, a, b, c) \
    asm("fma.rn.f32x2 %0, %1, %2, %3;" : "=l"(d) : "l"(a), "l"(b), "l"(c))
#define PACK_DUP_F32X2(d, s) \
    asm("mov.b64 %0, {%1, %2};" : "=l"(d) : "f"(s), "f"(s))
#define UNPACK_F32X2(lo, hi, in) \
    asm("mov.b64 {%0, %1}, %2;" : "=f"(lo), "=f"(hi) : "l"(in))

// ---------------------------------------------------------------------------
// GEMM: one node per thread, 16 f32x2 accumulators, W broadcast from smem via
// LDS.128. Block 0 additionally classifies the edge-index dtype (JAX x64-off
// hazard): reading genuine-int32 data as int64 words yields values >= 2^32
// whenever the odd 32-bit word is nonzero — over 256 words this is
// unambiguous for uniform indices in [0, 100000).
// z row (32 fp16 = 64B) is stored directly with 4 STG.128 per thread.
// ---------------------------------------------------------------------------
__global__ __launch_bounds__(GEMM_BLOCK)
void gemm_kernel(const float4* __restrict__ x4,
                 const float*  __restrict__ W,    // [128][32] row-major
                 const float*  __restrict__ b,    // [32]
                 __half2* __restrict__ zh,
                 int n_nodes,
                 const long long* __restrict__ idx_probe) {
    __shared__ float sW[IN_F * OUT_F];
    __shared__ int s_bad;

    int tid = threadIdx.x;

    #pragma unroll
    for (int i = tid; i < IN_F * OUT_F; i += GEMM_BLOCK) sW[i] = W[i];
    if (blockIdx.x == 0 && tid == 0) s_bad = 0;
    __syncthreads();

    // Index-dtype probe (block 0 only; hidden under this block's GEMM work).
    if (blockIdx.x == 0) {
        long long v = idx_probe[tid];
        if (v < 0 || v >= (long long)n_nodes) atomicOr(&s_bad, 1);
    }

    int node = blockIdx.x * GEMM_BLOCK + tid;

    // 16 packed f32x2 accumulators, initialized from bias pairs.
    unsigned long long acc[OUT_F / 2];
    const unsigned long long* b2 = (const unsigned long long*)b;
    #pragma unroll
    for (int o = 0; o < OUT_F / 2; o++) acc[o] = __ldg(&b2[o]);

    if (node < n_nodes) {
        const float4* xr = x4 + (size_t)node * (IN_F / 4);
        #pragma unroll 4
        for (int kk = 0; kk < IN_F / 4; kk++) {
            float4 xv = __ldg(&xr[kk]);
            float xs[4] = {xv.x, xv.y, xv.z, xv.w};
            #pragma unroll
            for (int j = 0; j < 4; j++) {
                unsigned long long ss;
                PACK_DUP_F32X2(ss, xs[j]);
                const float4* wr =
                    reinterpret_cast<const float4*>(sW + (kk * 4 + j) * OUT_F);
                #pragma unroll
                for (int o4 = 0; o4 < OUT_F / 4; o4++) {
                    float4 wv = wr[o4];                 // broadcast LDS.128
                    unsigned long long w0, w1;
                    asm("mov.b64 %0, {%1, %2};" : "=l"(w0) : "f"(wv.x), "f"(wv.y));
                    asm("mov.b64 %0, {%1, %2};" : "=l"(w1) : "f"(wv.z), "f"(wv.w));
                    FMA_F32X2(acc[2 * o4 + 0], ss, w0, acc[2 * o4 + 0]);
                    FMA_F32X2(acc[2 * o4 + 1], ss, w1, acc[2 * o4 + 1]);
                }
            }
        }

        // Convert to fp16 and store the 64B row (4 x STG.128).
        __half2 h[OUT_F / 2];
        #pragma unroll
        for (int o = 0; o < OUT_F / 2; o++) {
            float lo, hi;
            UNPACK_F32X2(lo, hi, acc[o]);
            h[o] = __floats2half2_rn(lo, hi);
        }
        uint4* zrow = reinterpret_cast<uint4*>(zh + (size_t)node * (OUT_F / 2));
        const uint4* hv = reinterpret_cast<const uint4*>(h);
        #pragma unroll
        for (int q = 0; q < 4; q++) zrow[q] = hv[q];
    }

    if (blockIdx.x == 0) {
        __syncthreads();
        if (tid == 0) g_idx64 = s_bad ? 0 : 1;
    }
}

// ---------------------------------------------------------------------------
// Edge kernel: 4 threads per edge, one uint4 (8 fp16) each — the 4-thread
// group covers the full 64B z row for r and c. Math in fp32.
// Indices/vals are read once -> __ldcs (evict-first, protect z in L2).
// Output is write-once   -> __stcs.
// ---------------------------------------------------------------------------
__global__ __launch_bounds__(256)
void edge_kernel(const __half2* __restrict__ zh,
                 const void* __restrict__ rows_raw,
                 const void* __restrict__ cols_raw,
                 const float* __restrict__ vals,
                 float4* __restrict__ out,
                 int n_edges) {
    int gid = blockIdx.x * blockDim.x + threadIdx.x;
    int e = gid >> 2;
    int c = gid & 3;
    if (e >= n_edges) return;

    long long r, cc;
    if (g_idx64) {
        r  = __ldcs(&((const long long*)rows_raw)[e]);
        cc = __ldcs(&((const long long*)cols_raw)[e]);
    } else {
        r  = __ldcs(&((const int*)rows_raw)[e]);
        cc = __ldcs(&((const int*)cols_raw)[e]);
    }
    float w = __ldcs(&vals[e]);

    const uint4* zr = reinterpret_cast<const uint4*>(zh + r  * (OUT_F / 2)) + c;
    const uint4* zc = reinterpret_cast<const uint4*>(zh + cc * (OUT_F / 2)) + c;
    uint4 a = __ldg(zr);
    uint4 d = __ldg(zc);

    float4 o0, o1;
    {
        float2 fa, fd;
        fa = __half22float2(*reinterpret_cast<__half2*>(&a.x));
        fd = __half22float2(*reinterpret_cast<__half2*>(&d.x));
        o0.x = w * (fa.x + fd.x);  o0.y = w * (fa.y + fd.y);
        fa = __half22float2(*reinterpret_cast<__half2*>(&a.y));
        fd = __half22float2(*reinterpret_cast<__half2*>(&d.y));
        o0.z = w * (fa.x + fd.x);  o0.w = w * (fa.y + fd.y);
        fa = __half22float2(*reinterpret_cast<__half2*>(&a.z));
        fd = __half22float2(*reinterpret_cast<__half2*>(&d.z));
        o1.x = w * (fa.x + fd.x);  o1.y = w * (fa.y + fd.y);
        fa = __half22float2(*reinterpret_cast<__half2*>(&a.w));
        fd = __half22float2(*reinterpret_cast<__half2*>(&d.w));
        o1.z = w * (fa.x + fd.x);  o1.w = w * (fa.y + fd.y);
    }

    float4* ob = out + (size_t)e * 8 + c * 2;
    __stcs(ob + 0, o0);
    __stcs(ob + 1, o1);
}

// ---------------------------------------------------------------------------
// Launch. Inputs (metadata order): x, W, b, edge_rows, edge_cols, edge_vals.
// ---------------------------------------------------------------------------
extern "C" void kernel_launch(void* const* d_in, const int* in_sizes, int n_in,
                              void* d_out, int out_size) {
    const float4* x4   = (const float4*)d_in[0];
    const float*  W    = (const float*)d_in[1];
    const float*  b    = (const float*)d_in[2];
    const void*   rows = d_in[3];
    const void*   cols = d_in[4];
    const float*  vals = (const float*)d_in[5];
    float4* out = (float4*)d_out;

    int n_nodes = in_sizes[0] / IN_F;
    int n_edges = in_sizes[3];

    __half2* zh = nullptr;
    cudaGetSymbolAddress((void**)&zh, g_zh);

    // 1) z = x @ W + b  (+ index-dtype probe in block 0)
    int gemm_blocks = (n_nodes + GEMM_BLOCK - 1) / GEMM_BLOCK;
    gemm_kernel<<<gemm_blocks, GEMM_BLOCK>>>(
        x4, W, b, zh, n_nodes, (const long long*)rows);

    // 2) out[e] = w_e * (z[r] + z[c])
    long long total = (long long)n_edges * 4;
    int edge_blocks = (int)((total + 255) / 256);
    edge_kernel<<<edge_blocks, 256>>>(zh, rows, cols, vals, out, n_edges);
}